// round 13
// baseline (speedup 1.0000x reference)
#include <cuda_runtime.h>

// Problem constants (fixed by the reference)
#define BB   4
#define CC   32
#define HH   64
#define WW   64
#define KK   64
#define HWV  (HH*WW)      // 4096
#define BCV  (BB*CC)      // 128
#define SEG  1024         // entries per segment (chunk of 1024 pixels)
#define CAP  4096         // per-k list capacity = 4 segments
#define NU   1024         // output units per image (32*32)

// ---------------- static device scratch (no allocation allowed) -------------
__device__ __align__(16) int g_pk[KK*CAP];   // per-k segmented lists {rf20|pix12}
__device__ int2  g_seg[KK*4];                // per segment {n128 (x128-padded), n}
__device__ int   g_uc [NU];                  // entries per unit (padded to x4)
__device__ __align__(16) int g_pxt[KK*NU*4]; // unit-major lists {rf25|k7}; k=64 null
__device__ float g_inv[BCV*KK];              // 1/(base + sum) per (bc,k)

__device__ __forceinline__ float ex2_fast(float y) {
    float r;
    asm("ex2.approx.f32 %0, %1;" : "=f"(r) : "f"(y));
    return r;
}

// ---------------- PREP (one launch, 320 blocks x 256 threads) ---------------
// blocks 0..255 : per-k segmented support lists. Block = (k, chunk c of 1024
//                 pixels). Independent blocks, raster order within segment,
//                 padded to x128 with {rf=0,pix=0} (each pad contributes
//                 exp(0)=1; denom subtracts pads exactly via g_seg).
// blocks 256..319: unit-major per-pixel lists, 4 threads/pixel, no barriers.
// All orders fixed, no atomics -> deterministic.
__global__ __launch_bounds__(256) void prep(const float* __restrict__ rfs) {
    const int tid = threadIdx.x;
    const float LOG2E = 1.4426950408889634f;

    if (blockIdx.x < 256) {
        const int k    = blockIdx.x >> 2;
        const int c    = blockIdx.x & 3;
        const int lane = tid & 31;
        const int wid  = tid >> 5;
        __shared__ int wtot[8];
        __shared__ int woff[8];
        __shared__ int sn;

        const float4 r = ((const float4*)(rfs + k*HWV + c*1024))[tid];
        const int f0 = (r.x != 0.0f), f1 = (r.y != 0.0f), f2 = (r.z != 0.0f), f3 = (r.w != 0.0f);
        const int cnt = f0 + f1 + f2 + f3;

        int s = cnt;                             // warp inclusive scan
        #pragma unroll
        for (int o = 1; o < 32; o <<= 1) {
            int t = __shfl_up_sync(0xffffffffu, s, o);
            if (lane >= o) s += t;
        }
        const int excl = s - cnt;
        if (lane == 31) wtot[wid] = s;
        __syncthreads();
        if (tid < 8) {                           // scan 8 warp totals
            int v = wtot[tid], ss = v;
            #pragma unroll
            for (int o = 1; o < 8; o <<= 1) {
                int t = __shfl_up_sync(0xffu, ss, o);
                if (tid >= o) ss += t;
            }
            woff[tid] = ss - v;
            if (tid == 7) sn = ss;
        }
        __syncthreads();

        int base = woff[wid] + excl;
        const int p0 = c*1024 + tid*4;
        int* __restrict__ dst = g_pk + k*CAP + c*SEG;
        #define PACK_A(val, pix) (((__float_as_int((val)*LOG2E) + 0x800) & 0xFFFFF000) | (pix))
        if (f0) { dst[base] = PACK_A(r.x, p0);     base++; }
        if (f1) { dst[base] = PACK_A(r.y, p0 + 1); base++; }
        if (f2) { dst[base] = PACK_A(r.z, p0 + 2); base++; }
        if (f3) { dst[base] = PACK_A(r.w, p0 + 3); base++; }
        #undef PACK_A

        const int n    = sn;                     // <= SEG
        const int n128 = (n + 127) & ~127;
        for (int j = n + tid; j < n128; j += 256) dst[j] = 0;   // pads
        if (tid == 0) g_seg[blockIdx.x] = make_int2(n128, n);
    } else {
        // px-list build: 64 blocks x 64 pixels; 4 threads per pixel.
        const int q  = tid & 3;                  // k-quarter (16 k)
        const int pl = tid >> 2;                 // pixel within block
        const int ug = (blockIdx.x - 256) * 16 + (pl >> 2);
        const int wn = pl & 3;                   // pixel within unit
        const int y  = 2*(ug >> 5) + (wn >> 1);
        const int x  = 2*(ug & 31) + (wn & 1);
        const int p  = y*WW + x;

        float rv[16];
        int cq = 0;
        #pragma unroll
        for (int i = 0; i < 16; i++) {
            rv[i] = rfs[(q*16 + i)*HWV + p];     // 16 independent LDGs
            cq += (rv[i] != 0.0f);
        }

        // exclusive prefix of cq over the 4-lane pixel group
        int off = 0;
        #pragma unroll
        for (int o = 1; o < 4; o++) {
            const int t = __shfl_up_sync(0xffffffffu, cq, o);
            if (q >= o) off += t;
        }
        // pixel total, then unit max over the 16-lane unit group
        int ct = cq;
        ct += __shfl_xor_sync(0xffffffffu, ct, 1);
        ct += __shfl_xor_sync(0xffffffffu, ct, 2);
        int cm = ct;
        cm = max(cm, __shfl_xor_sync(0xffffffffu, cm, 4));
        cm = max(cm, __shfl_xor_sync(0xffffffffu, cm, 8));
        const int cm4 = (cm + 3) & ~3;

        #pragma unroll
        for (int i = 0; i < 16; i++) {
            if (rv[i] != 0.0f) {
                const int k    = q*16 + i;
                const int bits = ((__float_as_int(rv[i]*LOG2E) + 0x40) & 0xFFFFFF80) | k;
                g_pxt[(off*NU + ug)*4 + wn] = bits;
                off++;
            }
        }
        if (q == 3) {                            // off == ct here; pad to cm4
            for (int j = ct; j < cm4; j++)
                g_pxt[(j*NU + ug)*4 + wn] = 64;  // null: rf=+0, k=64 -> 0
            if (wn == 0) g_uc[ug] = cm4;
        }
    }
}

// ---------------- K_A: denominators, warp-per-(bc,k), int4 lists ------------
// exp(v - m)/(exp(-m) + sum exp(v - m)) == exp(v)/(1 + sum exp(v)).
// Lane loads 4 consecutive entries (LDG.128); entries are raster-ordered so
// the 4 gathers hit consecutive pixels -> near-perfect sector efficiency.
// Segment lengths are multiples of 128 -> branch-free warp loops.
__global__ __launch_bounds__(256) void k_denom(const float* __restrict__ u) {
    const int bc   = blockIdx.x >> 3;
    const int kc   = blockIdx.x & 7;
    const int lane = threadIdx.x & 31;
    const int k    = kc*8 + (threadIdx.x >> 5);

    const float* __restrict__ ub = u + bc*HWV;
    float base = 1.0f;
    float s0 = 0.0f, s1 = 0.0f, s2 = 0.0f, s3 = 0.0f;

    #pragma unroll
    for (int c = 0; c < 4; c++) {
        const int2 t = g_seg[k*4 + c];
        base -= (float)(t.x - t.y);                       // exact pad correction
        const int4* __restrict__ pr = (const int4*)(g_pk + k*CAP + c*SEG);
        const int nq = t.x >> 2;                          // multiple of 32
        for (int j = lane; j < nq; j += 32) {
            const int4 b = pr[j];                         // LDG.128
            s0 += ex2_fast(ub[b.x & 0xFFF] * __int_as_float(b.x & 0xFFFFF000));
            s1 += ex2_fast(ub[b.y & 0xFFF] * __int_as_float(b.y & 0xFFFFF000));
            s2 += ex2_fast(ub[b.z & 0xFFF] * __int_as_float(b.z & 0xFFFFF000));
            s3 += ex2_fast(ub[b.w & 0xFFF] * __int_as_float(b.w & 0xFFFFF000));
        }
    }
    float sum = (s0 + s1) + (s2 + s3);
    #pragma unroll
    for (int o = 16; o > 0; o >>= 1) sum += __shfl_down_sync(0xffffffffu, sum, o);
    if (lane == 0) g_inv[bc*KK + k] = 1.0f / (base + sum);
}

// ---------------- K_B: per-unit numerators + max, direct store --------------
// Thread = one output unit: 4 register accumulators (its 2x2 pixels), one
// coalesced LDG.128 per list entry-row, unrolled x4 (16 entries in flight).
__global__ __launch_bounds__(256) void k_numer(const float* __restrict__ u,
                                               float* __restrict__ out) {
    __shared__ float inv_s[128];     // [64..127] = 0 for null entries

    const int bc  = blockIdx.x >> 2;
    const int seg = blockIdx.x & 3;
    const int tid = threadIdx.x;

    if (tid < 64)        inv_s[tid] = g_inv[bc*KK + tid];
    else if (tid < 128)  inv_s[tid] = 0.0f;
    __syncthreads();

    const int ug = seg*256 + tid;                // global unit
    const int gb = bc*HWV + 2*(ug >> 5)*WW + 2*(ug & 31);
    const float u0 = u[gb], u1 = u[gb + 1], u2 = u[gb + WW], u3 = u[gb + WW + 1];
    const int cn = g_uc[ug];                     // multiple of 4

    const int4* __restrict__ PT = (const int4*)g_pxt;
    float a0 = 0.0f, a1 = 0.0f, a2 = 0.0f, a3 = 0.0f;

    #define RFV(b) __int_as_float((b) & 0xFFFFFF80)
    for (int j = 0; j < cn; j += 4) {
        const int4 b0 = PT[(j + 0)*NU + ug];     // 4 independent LDG.128,
        const int4 b1 = PT[(j + 1)*NU + ug];     // perfectly lane-coalesced
        const int4 b2 = PT[(j + 2)*NU + ug];
        const int4 b3 = PT[(j + 3)*NU + ug];
        a0 += ex2_fast(u0 * RFV(b0.x)) * inv_s[b0.x & 127];
        a1 += ex2_fast(u1 * RFV(b0.y)) * inv_s[b0.y & 127];
        a2 += ex2_fast(u2 * RFV(b0.z)) * inv_s[b0.z & 127];
        a3 += ex2_fast(u3 * RFV(b0.w)) * inv_s[b0.w & 127];
        a0 += ex2_fast(u0 * RFV(b1.x)) * inv_s[b1.x & 127];
        a1 += ex2_fast(u1 * RFV(b1.y)) * inv_s[b1.y & 127];
        a2 += ex2_fast(u2 * RFV(b1.z)) * inv_s[b1.z & 127];
        a3 += ex2_fast(u3 * RFV(b1.w)) * inv_s[b1.w & 127];
        a0 += ex2_fast(u0 * RFV(b2.x)) * inv_s[b2.x & 127];
        a1 += ex2_fast(u1 * RFV(b2.y)) * inv_s[b2.y & 127];
        a2 += ex2_fast(u2 * RFV(b2.z)) * inv_s[b2.z & 127];
        a3 += ex2_fast(u3 * RFV(b2.w)) * inv_s[b2.w & 127];
        a0 += ex2_fast(u0 * RFV(b3.x)) * inv_s[b3.x & 127];
        a1 += ex2_fast(u1 * RFV(b3.y)) * inv_s[b3.y & 127];
        a2 += ex2_fast(u2 * RFV(b3.z)) * inv_s[b3.z & 127];
        a3 += ex2_fast(u3 * RFV(b3.w)) * inv_s[b3.w & 127];
    }
    #undef RFV

    const float best = fmaxf(fmaxf(fmaxf(a0, a1), fmaxf(a2, a3)), 0.0f);
    out[bc*NU + ug] = best;
}

// ---------------- launch -----------------------------------------------------
extern "C" void kernel_launch(void* const* d_in, const int* in_sizes, int n_in,
                              void* d_out, int out_size) {
    const float* u   = (const float*)d_in[0];   // (4,32,64,64)
    const float* rfs = (const float*)d_in[1];   // (64,64,64)
    float* out = (float*)d_out;                 // (4,32,32,32)

    prep   <<<320,   256>>>(rfs);
    k_denom<<<BCV*8, 256>>>(u);
    k_numer<<<BCV*4, 256>>>(u, out);
}

// round 15
// speedup vs baseline: 1.0779x; 1.0779x over previous
#include <cuda_runtime.h>

// Problem constants (fixed by the reference)
#define BB   4
#define CC   32
#define HH   64
#define WW   64
#define KK   64
#define HWV  (HH*WW)      // 4096
#define BCV  (BB*CC)      // 128
#define SEG  1024         // entries per segment (chunk of 1024 pixels)
#define CAP  4096         // per-k list capacity = 4 segments
#define NU   1024         // output units per image (32*32)

// ---------------- static device scratch (no allocation allowed) -------------
__device__ __align__(16) int g_pk[KK*CAP];   // per-k segmented lists {rf20|pix12}
__device__ int2  g_seg[KK*4];                // per segment {n128 (x128-padded), n}
__device__ int   g_uc [NU];                  // entries per unit (padded to x4)
__device__ __align__(16) int g_pxt[KK*NU*4]; // unit-major lists {rf25|k7}; k=64 null
__device__ float g_inv[BCV*KK];              // 1/(base + sum) per (bc,k)

__device__ __forceinline__ float ex2_fast(float y) {
    float r;
    asm("ex2.approx.f32 %0, %1;" : "=f"(r) : "f"(y));
    return r;
}

// ---------------- P1: per-k segmented support lists (256 blocks) ------------
// Block = (k, chunk c of 1024 pixels). Raster order within segment, padded to
// x128 with {rf=0,pix=0} (pad contributes exp(0)=1; denom subtracts exactly
// via g_seg). Fixed orders, no atomics -> deterministic.
__global__ __launch_bounds__(256) void prep_k(const float* __restrict__ rfs) {
    const int tid  = threadIdx.x;
    const int k    = blockIdx.x >> 2;
    const int c    = blockIdx.x & 3;
    const int lane = tid & 31;
    const int wid  = tid >> 5;
    __shared__ int wtot[8];
    __shared__ int woff[8];
    __shared__ int sn;

    const float LOG2E = 1.4426950408889634f;

    const float4 r = ((const float4*)(rfs + k*HWV + c*1024))[tid];
    const int f0 = (r.x != 0.0f), f1 = (r.y != 0.0f), f2 = (r.z != 0.0f), f3 = (r.w != 0.0f);
    const int cnt = f0 + f1 + f2 + f3;

    int s = cnt;                             // warp inclusive scan (running value)
    #pragma unroll
    for (int o = 1; o < 32; o <<= 1) {
        int t = __shfl_up_sync(0xffffffffu, s, o);
        if (lane >= o) s += t;
    }
    const int excl = s - cnt;
    if (lane == 31) wtot[wid] = s;
    __syncthreads();
    if (tid < 8) {                           // scan 8 warp totals
        int v = wtot[tid], ss = v;
        #pragma unroll
        for (int o = 1; o < 8; o <<= 1) {
            int t = __shfl_up_sync(0xffu, ss, o);
            if (tid >= o) ss += t;
        }
        woff[tid] = ss - v;
        if (tid == 7) sn = ss;
    }
    __syncthreads();

    int base = woff[wid] + excl;
    const int p0 = c*1024 + tid*4;
    int* __restrict__ dst = g_pk + k*CAP + c*SEG;
    #define PACK_A(val, pix) (((__float_as_int((val)*LOG2E) + 0x800) & 0xFFFFF000) | (pix))
    if (f0) { dst[base] = PACK_A(r.x, p0);     base++; }
    if (f1) { dst[base] = PACK_A(r.y, p0 + 1); base++; }
    if (f2) { dst[base] = PACK_A(r.z, p0 + 2); base++; }
    if (f3) { dst[base] = PACK_A(r.w, p0 + 3); base++; }
    #undef PACK_A

    const int n    = sn;                     // <= SEG
    const int n128 = (n + 127) & ~127;
    for (int j = n + tid; j < n128; j += 256) dst[j] = 0;   // pads
    if (tid == 0) g_seg[blockIdx.x] = make_int2(n128, n);
}

// ---------------- K_A: denominators x4 bc (blocks 0..255) + px build --------
// (blocks 256..383; depends only on rfs, so it overlaps the denom blocks).
// Denominators: exp(v-m)/(exp(-m)+sum exp(v-m)) == exp(v)/(1+sum exp(v)).
// Warp = one k for FOUR images: each list entry loaded once feeds 4
// independent gather+exp chains -> 4x work per long-latency list load.
__global__ __launch_bounds__(256) void denom_px(const float* __restrict__ u,
                                                const float* __restrict__ rfs) {
    const int tid = threadIdx.x;

    if (blockIdx.x < 256) {
        const int bcg  = blockIdx.x >> 3;        // group of 4 images
        const int kc   = blockIdx.x & 7;
        const int lane = tid & 31;
        const int k    = kc*8 + (tid >> 5);

        const float* __restrict__ ub0 = u + (bcg*4 + 0)*HWV;
        const float* __restrict__ ub1 = u + (bcg*4 + 1)*HWV;
        const float* __restrict__ ub2 = u + (bcg*4 + 2)*HWV;
        const float* __restrict__ ub3 = u + (bcg*4 + 3)*HWV;

        float base = 1.0f;
        float s0 = 0.0f, s1 = 0.0f, s2 = 0.0f, s3 = 0.0f;

        #pragma unroll
        for (int c = 0; c < 4; c++) {
            const int2 t = g_seg[k*4 + c];
            base -= (float)(t.x - t.y);          // exact pad correction
            const int4* __restrict__ pr = (const int4*)(g_pk + k*CAP + c*SEG);
            const int nq = t.x >> 2;             // multiple of 32
            for (int j = lane; j < nq; j += 32) {
                const int4 b = pr[j];            // LDG.128, raster-ordered
                const float r0 = __int_as_float(b.x & 0xFFFFF000);
                const float r1 = __int_as_float(b.y & 0xFFFFF000);
                const float r2 = __int_as_float(b.z & 0xFFFFF000);
                const float r3 = __int_as_float(b.w & 0xFFFFF000);
                const int   p0 = b.x & 0xFFF, p1 = b.y & 0xFFF;
                const int   p2 = b.z & 0xFFF, p3 = b.w & 0xFFF;
                s0 += ex2_fast(ub0[p0]*r0) + ex2_fast(ub0[p1]*r1)
                    + ex2_fast(ub0[p2]*r2) + ex2_fast(ub0[p3]*r3);
                s1 += ex2_fast(ub1[p0]*r0) + ex2_fast(ub1[p1]*r1)
                    + ex2_fast(ub1[p2]*r2) + ex2_fast(ub1[p3]*r3);
                s2 += ex2_fast(ub2[p0]*r0) + ex2_fast(ub2[p1]*r1)
                    + ex2_fast(ub2[p2]*r2) + ex2_fast(ub2[p3]*r3);
                s3 += ex2_fast(ub3[p0]*r0) + ex2_fast(ub3[p1]*r1)
                    + ex2_fast(ub3[p2]*r2) + ex2_fast(ub3[p3]*r3);
            }
        }
        #pragma unroll
        for (int o = 16; o > 0; o >>= 1) {
            s0 += __shfl_down_sync(0xffffffffu, s0, o);
            s1 += __shfl_down_sync(0xffffffffu, s1, o);
            s2 += __shfl_down_sync(0xffffffffu, s2, o);
            s3 += __shfl_down_sync(0xffffffffu, s3, o);
        }
        if (lane == 0) {
            g_inv[(bcg*4 + 0)*KK + k] = 1.0f / (base + s0);
            g_inv[(bcg*4 + 1)*KK + k] = 1.0f / (base + s1);
            g_inv[(bcg*4 + 2)*KK + k] = 1.0f / (base + s2);
            g_inv[(bcg*4 + 3)*KK + k] = 1.0f / (base + s3);
        }
    } else {
        // px-list build: 128 blocks x 8 units; warp = unit; 8 threads/pixel,
        // 8 k each (k = t*8+i, t-major ascending -> fixed order).
        const float LOG2E = 1.4426950408889634f;
        const int lane = tid & 31;
        const int wn   = lane >> 3;              // pixel within unit (0..3)
        const int t    = lane & 7;               // k-octet (0..7)
        const int ug   = (blockIdx.x - 256)*8 + (tid >> 5);
        const int y    = 2*(ug >> 5) + (wn >> 1);
        const int x    = 2*(ug & 31) + (wn & 1);
        const int p    = y*WW + x;

        float rv[8];
        int cq = 0;
        #pragma unroll
        for (int i = 0; i < 8; i++) {
            rv[i] = rfs[(t*8 + i)*HWV + p];      // 8 independent LDGs
            cq += (rv[i] != 0.0f);
        }

        // CORRECT exclusive prefix over the 8-lane pixel group: Hillis-Steele
        // inclusive scan of the RUNNING value, then subtract own count.
        // shfl_up never crosses the 8-lane group (only used when t >= o).
        int sc = cq;
        #pragma unroll
        for (int o = 1; o < 8; o <<= 1) {
            const int v = __shfl_up_sync(0xffffffffu, sc, o);
            if (t >= o) sc += v;
        }
        int off = sc - cq;

        // pixel total (sum over aligned 8-group), then unit max
        int ct = cq;
        ct += __shfl_xor_sync(0xffffffffu, ct, 1);
        ct += __shfl_xor_sync(0xffffffffu, ct, 2);
        ct += __shfl_xor_sync(0xffffffffu, ct, 4);
        int cm = ct;
        cm = max(cm, __shfl_xor_sync(0xffffffffu, cm, 8));
        cm = max(cm, __shfl_xor_sync(0xffffffffu, cm, 16));
        const int cm4 = (cm + 3) & ~3;

        #pragma unroll
        for (int i = 0; i < 8; i++) {
            if (rv[i] != 0.0f) {
                const int k    = t*8 + i;
                const int bits = ((__float_as_int(rv[i]*LOG2E) + 0x40) & 0xFFFFFF80) | k;
                g_pxt[(off*NU + ug)*4 + wn] = bits;
                off++;
            }
        }
        if (t == 7) {                            // off == ct here; pad to cm4
            for (int j = ct; j < cm4; j++)
                g_pxt[(j*NU + ug)*4 + wn] = 64;  // null: rf=+0, k=64 -> 0
            if (wn == 0) g_uc[ug] = cm4;
        }
    }
}

// ---------------- K_B: per-unit numerators x2 bc + max, direct store --------
// Thread = one output unit for TWO images: each list row loaded once feeds
// 2 independent exp/FMA chains; inv lookup is one LDS.64 covering both.
__global__ __launch_bounds__(256) void k_numer(const float* __restrict__ u,
                                               float* __restrict__ out) {
    __shared__ float2 inv2[128];     // [64..127] = 0 for null entries

    const int bcg = blockIdx.x >> 2;             // group of 2 images (0..63)
    const int seg = blockIdx.x & 3;
    const int bc0 = bcg*2;
    const int tid = threadIdx.x;

    if (tid < 64)
        inv2[tid] = make_float2(g_inv[bc0*KK + tid], g_inv[(bc0+1)*KK + tid]);
    else if (tid < 128)
        inv2[tid] = make_float2(0.0f, 0.0f);
    __syncthreads();

    const int ug = seg*256 + tid;                // global unit
    const int gb = 2*(ug >> 5)*WW + 2*(ug & 31);
    const float* __restrict__ ua = u + bc0*HWV;
    const float* __restrict__ ub = ua + HWV;
    const float ua0 = ua[gb], ua1 = ua[gb+1], ua2 = ua[gb+WW], ua3 = ua[gb+WW+1];
    const float ub0 = ub[gb], ub1 = ub[gb+1], ub2 = ub[gb+WW], ub3 = ub[gb+WW+1];
    const int cn = g_uc[ug];                     // multiple of 4

    const int4* __restrict__ PT = (const int4*)g_pxt;
    float A0 = 0.0f, A1 = 0.0f, A2 = 0.0f, A3 = 0.0f;
    float B0 = 0.0f, B1 = 0.0f, B2 = 0.0f, B3 = 0.0f;

    #define DO_ROW(r)  do {                                                   \
        const float r0 = __int_as_float((r).x & 0xFFFFFF80);                  \
        const float r1 = __int_as_float((r).y & 0xFFFFFF80);                  \
        const float r2 = __int_as_float((r).z & 0xFFFFFF80);                  \
        const float r3 = __int_as_float((r).w & 0xFFFFFF80);                  \
        const float2 i0 = inv2[(r).x & 127];                                  \
        const float2 i1 = inv2[(r).y & 127];                                  \
        const float2 i2 = inv2[(r).z & 127];                                  \
        const float2 i3 = inv2[(r).w & 127];                                  \
        A0 += ex2_fast(ua0*r0)*i0.x;  B0 += ex2_fast(ub0*r0)*i0.y;            \
        A1 += ex2_fast(ua1*r1)*i1.x;  B1 += ex2_fast(ub1*r1)*i1.y;            \
        A2 += ex2_fast(ua2*r2)*i2.x;  B2 += ex2_fast(ub2*r2)*i2.y;            \
        A3 += ex2_fast(ua3*r3)*i3.x;  B3 += ex2_fast(ub3*r3)*i3.y;            \
    } while (0)

    for (int j = 0; j < cn; j += 4) {
        const int4 b0 = PT[(j + 0)*NU + ug];     // 4 independent LDG.128,
        const int4 b1 = PT[(j + 1)*NU + ug];     // perfectly lane-coalesced
        const int4 b2 = PT[(j + 2)*NU + ug];
        const int4 b3 = PT[(j + 3)*NU + ug];
        DO_ROW(b0); DO_ROW(b1); DO_ROW(b2); DO_ROW(b3);
    }
    #undef DO_ROW

    const float bestA = fmaxf(fmaxf(fmaxf(A0, A1), fmaxf(A2, A3)), 0.0f);
    const float bestB = fmaxf(fmaxf(fmaxf(B0, B1), fmaxf(B2, B3)), 0.0f);
    out[ bc0     *NU + ug] = bestA;
    out[(bc0 + 1)*NU + ug] = bestB;
}

// ---------------- launch -----------------------------------------------------
extern "C" void kernel_launch(void* const* d_in, const int* in_sizes, int n_in,
                              void* d_out, int out_size) {
    const float* u   = (const float*)d_in[0];   // (4,32,64,64)
    const float* rfs = (const float*)d_in[1];   // (64,64,64)
    float* out = (float*)d_out;                 // (4,32,32,32)

    prep_k  <<<256,       256>>>(rfs);
    denom_px<<<256 + 128, 256>>>(u, rfs);
    k_numer <<<256,       256>>>(u, out);
}